// round 11
// baseline (speedup 1.0000x reference)
#include <cuda_runtime.h>
#include <cuda_bf16.h>
#include <cstdint>

#define LSEQ 8192
#define FIN  1024
#define CDIM 256
#define C3   768
#define NH   8
#define DH   32
#define KS   63

__device__ float g_y[LSEQ * CDIM];
__device__ float g_qkv[LSEQ * C3];
__device__ float g_att[LSEQ * CDIM];
__device__ float g_part[4 * LSEQ * CDIM];   // split-K partials (32 MB)

// Pre-rounded (tf32 RNE) weights, original [K][N] layout
__device__ float g_Wp_r[FIN * CDIM];
__device__ float g_Wq_r[CDIM * C3];
__device__ float g_Wo_r[CDIM * CDIM];

// ---------------------------------------------------------------------------
// helpers
// ---------------------------------------------------------------------------
__device__ __forceinline__ void cp16(void* smem, const void* g) {
    uint32_t s = (uint32_t)__cvta_generic_to_shared(smem);
    asm volatile("cp.async.cg.shared.global [%0], [%1], 16;\n" :: "r"(s), "l"(g));
}
__device__ __forceinline__ void cp_commit() {
    asm volatile("cp.async.commit_group;\n");
}
__device__ __forceinline__ void mma_tf32(float* d, const uint32_t* a, const uint32_t* b) {
    asm volatile(
        "mma.sync.aligned.m16n8k8.row.col.f32.tf32.tf32.f32 "
        "{%0,%1,%2,%3}, {%4,%5,%6,%7}, {%8,%9}, {%0,%1,%2,%3};\n"
        : "+f"(d[0]), "+f"(d[1]), "+f"(d[2]), "+f"(d[3])
        : "r"(a[0]), "r"(a[1]), "r"(a[2]), "r"(a[3]), "r"(b[0]), "r"(b[1]));
}
__device__ __forceinline__ uint32_t cvt_rna_tf32(float x) {
    uint32_t r;
    asm("cvt.rna.tf32.f32 %0, %1;" : "=r"(r) : "f"(x));
    return r;
}
__device__ __forceinline__ float round_tf32(float x) {
    return __uint_as_float(cvt_rna_tf32(x));
}

// ---------------------------------------------------------------------------
// Weight prep: round W to tf32 (RNE)
// ---------------------------------------------------------------------------
__global__ void prep_weights_kernel(const float* __restrict__ W,
                                    float* __restrict__ Wr, int total)
{
    int idx = blockIdx.x * blockDim.x + threadIdx.x;
    if (idx >= total) return;
    Wr[idx] = round_tf32(W[idx]);
}

// ---------------------------------------------------------------------------
// Split-K reduce: out = sum(parts) + bias, optional tf32 round. float4.
// ---------------------------------------------------------------------------
template<int SPLITK, bool ROUND>
__global__ void reduce_kernel(const float* __restrict__ part,
                              const float* __restrict__ bias,
                              float* __restrict__ out, int M, int N)
{
    int idx4 = blockIdx.x * blockDim.x + threadIdx.x;
    int total4 = (M * N) >> 2;
    if (idx4 >= total4) return;
    float4 v = ((const float4*)part)[idx4];
    #pragma unroll
    for (int s = 1; s < SPLITK; s++) {
        float4 p = ((const float4*)(part + (size_t)s * M * N))[idx4];
        v.x += p.x; v.y += p.y; v.z += p.z; v.w += p.w;
    }
    int col = (idx4 << 2) % N;
    float4 b = *(const float4*)&bias[col];
    v.x += b.x; v.y += b.y; v.z += b.z; v.w += b.w;
    if (ROUND) {
        v.x = round_tf32(v.x); v.y = round_tf32(v.y);
        v.z = round_tf32(v.z); v.w = round_tf32(v.w);
    }
    ((float4*)out)[idx4] = v;
}

// ---------------------------------------------------------------------------
// TF32 GEMM v2: BM=128 BN=128 BK=16, 256 thr, 8 warps (2m x 4n),
// warp tile 64x32 (mi=4, nj=4), m16n8k8, 4-stage cp.async, optional split-K.
// ---------------------------------------------------------------------------
#define ASTRIDE 20
#define BSTRIDE 136
#define NSTAGE 4
#define ABYTES (128 * ASTRIDE * 4)       // 10240
#define BBYTES (16 * BSTRIDE * 4)        // 8704
#define STAGEB (ABYTES + BBYTES)         // 18944
#define GSMEM  (NSTAGE * STAGEB)         // 75776

template<bool CVT_A, bool ROUND_OUT, int SPLITK>
__global__ __launch_bounds__(256) void gemm_tf32_kernel(
    const float* __restrict__ A, const float* __restrict__ B,
    const float* __restrict__ bias, float* __restrict__ C,
    int M, int N, int K)
{
    extern __shared__ char smem[];

    const int bm = blockIdx.y * 128;
    const int bn = blockIdx.x * 128;
    const int kslice = (SPLITK > 1) ? blockIdx.z : 0;
    const int Kloc = K / SPLITK;
    const int kbase = kslice * Kloc;

    const int tid = threadIdx.x;
    const int wid = tid >> 5;
    const int lane = tid & 31;
    const int warp_m = wid & 1;     // 0..1 -> 64 rows each
    const int warp_n = wid >> 1;    // 0..3 -> 32 cols each
    const int r = lane >> 2;
    const int c = lane & 3;

    const int arow = tid >> 1;              // 0..127
    const int ac8  = (tid & 1) * 8;         // 0 or 8
    const int brow = tid >> 4;              // 0..15
    const int bc8  = (tid & 15) * 8;

    float acc[4][4][4];
    #pragma unroll
    for (int i = 0; i < 4; i++)
        #pragma unroll
        for (int j = 0; j < 4; j++)
            #pragma unroll
            for (int e = 0; e < 4; e++) acc[i][j][e] = 0.f;

    const int T = Kloc >> 4;

    auto stage = [&](int kt, int s) {
        float* As = (float*)(smem + s * STAGEB);
        float* Bs = (float*)(smem + s * STAGEB + ABYTES);
        const int k0 = kbase + (kt << 4);
        cp16(&As[arow * ASTRIDE + ac8],     &A[(size_t)(bm + arow) * K + k0 + ac8]);
        cp16(&As[arow * ASTRIDE + ac8 + 4], &A[(size_t)(bm + arow) * K + k0 + ac8 + 4]);
        cp16(&Bs[brow * BSTRIDE + bc8],     &B[(size_t)(k0 + brow) * N + bn + bc8]);
        cp16(&Bs[brow * BSTRIDE + bc8 + 4], &B[(size_t)(k0 + brow) * N + bn + bc8 + 4]);
        cp_commit();
    };

    stage(0, 0);
    stage(1, 1);
    stage(2, 2);

    for (int i = 0; i < T; i++) {
        const int s = i & 3;
        asm volatile("cp.async.wait_group 2;\n");
        __syncthreads();

        const float* as = (const float*)(smem + s * STAGEB);
        const float* bs = (const float*)(smem + s * STAGEB + ABYTES);

        #pragma unroll
        for (int ks = 0; ks < 16; ks += 8) {
            uint32_t af[4][4], bf[4][2];
            #pragma unroll
            for (int mi = 0; mi < 4; mi++) {
                int m0 = warp_m * 64 + mi * 16;
                float a0 = as[(m0 + r)     * ASTRIDE + ks + c];
                float a1 = as[(m0 + r + 8) * ASTRIDE + ks + c];
                float a2 = as[(m0 + r)     * ASTRIDE + ks + c + 4];
                float a3 = as[(m0 + r + 8) * ASTRIDE + ks + c + 4];
                if (CVT_A) {
                    af[mi][0] = cvt_rna_tf32(a0);
                    af[mi][1] = cvt_rna_tf32(a1);
                    af[mi][2] = cvt_rna_tf32(a2);
                    af[mi][3] = cvt_rna_tf32(a3);
                } else {
                    af[mi][0] = __float_as_uint(a0);
                    af[mi][1] = __float_as_uint(a1);
                    af[mi][2] = __float_as_uint(a2);
                    af[mi][3] = __float_as_uint(a3);
                }
            }
            #pragma unroll
            for (int nj = 0; nj < 4; nj++) {
                int n0 = warp_n * 32 + nj * 8 + r;
                bf[nj][0] = __float_as_uint(bs[(ks + c)     * BSTRIDE + n0]);
                bf[nj][1] = __float_as_uint(bs[(ks + c + 4) * BSTRIDE + n0]);
            }
            #pragma unroll
            for (int mi = 0; mi < 4; mi++)
                #pragma unroll
                for (int nj = 0; nj < 4; nj++)
                    mma_tf32(acc[mi][nj], af[mi], bf[nj]);
        }

        if (i + 3 < T) stage(i + 3, (i + 3) & 3);
        else cp_commit();
    }

    float* Cb = (SPLITK > 1) ? (C + (size_t)kslice * M * N) : C;
    #pragma unroll
    for (int mi = 0; mi < 4; mi++) {
        #pragma unroll
        for (int nj = 0; nj < 4; nj++) {
            int row = bm + warp_m * 64 + mi * 16 + r;
            int col = bn + warp_n * 32 + nj * 8 + c * 2;
            float2 o0, o1;
            o0.x = acc[mi][nj][0]; o0.y = acc[mi][nj][1];
            o1.x = acc[mi][nj][2]; o1.y = acc[mi][nj][3];
            if (SPLITK == 1) {
                float2 bb = *(const float2*)&bias[col];
                o0.x += bb.x; o0.y += bb.y;
                o1.x += bb.x; o1.y += bb.y;
                if (ROUND_OUT) {
                    o0.x = round_tf32(o0.x); o0.y = round_tf32(o0.y);
                    o1.x = round_tf32(o1.x); o1.y = round_tf32(o1.y);
                }
            }
            *(float2*)&Cb[(size_t)row * N + col] = o0;
            *(float2*)&Cb[(size_t)(row + 8) * N + col] = o1;
        }
    }
}

// ---------------------------------------------------------------------------
// NATTEN-1D (unchanged; att stored tf32-pre-rounded for GEMM3)
// ---------------------------------------------------------------------------
#define TQ 64
#define KV 126
#define RS 36
#define PTS 12
#define PTROWS 72

__device__ __forceinline__ int win_start(int l) {
    int s = l - 31;
    if (s < 0) s = 0;
    if (s > LSEQ - KS) s = LSEQ - KS;
    return s;
}

__global__ __launch_bounds__(256) void natten_kernel(
    const float* __restrict__ qkv, float* __restrict__ out)
{
    extern __shared__ float sm[];
    float* Ks = sm;
    float* Vs = Ks + 127 * RS;
    float* Qs = Vs + 127 * RS;
    float* Pt = Qs + TQ * RS;

    const int t0 = blockIdx.x * TQ;
    const int h = blockIdx.y;
    const int tid = threadIdx.x;
    const int w = tid >> 5;
    const int lane = tid & 31;

    int base = t0 - 31;
    if (base < 0) base = 0;
    if (base > LSEQ - KV) base = LSEQ - KV;

    const float scale = 0.17677669529663687f;

    for (int idx = tid; idx < KV * 32; idx += 256) {
        int row = idx >> 5;
        int d = idx & 31;
        size_t g = (size_t)(base + row) * C3 + CDIM + h * DH + d;
        Ks[row * RS + d] = qkv[g];
        Vs[row * RS + d] = qkv[g + CDIM];
    }
    if (tid < 32) {
        Ks[126 * RS + tid] = 0.f;
        Vs[126 * RS + tid] = 0.f;
    }
    for (int idx = tid; idx < TQ * 32; idx += 256) {
        int row = idx >> 5;
        int d = idx & 31;
        Qs[row * RS + d] = qkv[(size_t)(t0 + row) * C3 + h * DH + d] * scale;
    }
    for (int idx = tid; idx < 8 * PTROWS * PTS; idx += 256)
        Pt[idx] = 0.f;
    __syncthreads();

    const int l0 = t0 + w * 8;
    const int ws0 = win_start(l0) - base;
    const int ws7 = win_start(l0 + 7) - base;
    float* Ptw = Pt + w * PTROWS * PTS;

    #pragma unroll 1
    for (int qi = 0; qi < 8; qi++) {
        const int lq = w * 8 + qi;
        const int l = t0 + lq;
        const int ws = win_start(l) - base;

        const float4* k0p = (const float4*)&Ks[(ws + lane) * RS];
        const float4* k1p = (const float4*)&Ks[(ws + 32 + lane) * RS];
        const float4* qp  = (const float4*)&Qs[lq * RS];

        float s0 = 0.f, s1 = 0.f;
        #pragma unroll
        for (int d4 = 0; d4 < 8; d4++) {
            float4 q4 = qp[d4];
            float4 ka = k0p[d4];
            float4 kb = k1p[d4];
            s0 += q4.x * ka.x + q4.y * ka.y + q4.z * ka.z + q4.w * ka.w;
            s1 += q4.x * kb.x + q4.y * kb.y + q4.z * kb.z + q4.w * kb.w;
        }

        float m = fmaxf(s0, (lane < 31) ? s1 : -1e30f);
        #pragma unroll
        for (int o = 16; o > 0; o >>= 1)
            m = fmaxf(m, __shfl_xor_sync(0xffffffffu, m, o));
        float e0 = __expf(s0 - m);
        float e1 = (lane < 31) ? __expf(s1 - m) : 0.f;
        float sum = e0 + e1;
        #pragma unroll
        for (int o = 16; o > 0; o >>= 1)
            sum += __shfl_xor_sync(0xffffffffu, sum, o);
        float inv = __frcp_rn(sum);

        const int off = ws - ws0;
        Ptw[(off + lane) * PTS + qi]      = e0 * inv;
        Ptw[(off + 32 + lane) * PTS + qi] = e1 * inv;
    }
    __syncwarp();

    const int nU = ws7 - ws0 + 64;
    float acc[8];
    #pragma unroll
    for (int q = 0; q < 8; q++) acc[q] = 0.f;

    const float* vb = &Vs[ws0 * RS + lane];
    #pragma unroll 4
    for (int jj = 0; jj < nU; jj++) {
        float v = vb[jj * RS];
        float4 pa = *(const float4*)&Ptw[jj * PTS];
        float4 pb = *(const float4*)&Ptw[jj * PTS + 4];
        acc[0] = fmaf(pa.x, v, acc[0]);
        acc[1] = fmaf(pa.y, v, acc[1]);
        acc[2] = fmaf(pa.z, v, acc[2]);
        acc[3] = fmaf(pa.w, v, acc[3]);
        acc[4] = fmaf(pb.x, v, acc[4]);
        acc[5] = fmaf(pb.y, v, acc[5]);
        acc[6] = fmaf(pb.z, v, acc[6]);
        acc[7] = fmaf(pb.w, v, acc[7]);
    }

    #pragma unroll
    for (int q = 0; q < 8; q++)
        out[(size_t)(l0 + q) * CDIM + h * DH + lane] = round_tf32(acc[q]);
}

// ---------------------------------------------------------------------------
extern "C" void kernel_launch(void* const* d_in, const int* in_sizes, int n_in,
                              void* d_out, int out_size)
{
    const float* x    = (const float*)d_in[0];
    const float* Wp   = (const float*)d_in[1];
    const float* bp   = (const float*)d_in[2];
    const float* Wqkv = (const float*)d_in[3];
    const float* bqkv = (const float*)d_in[4];
    const float* Wo   = (const float*)d_in[5];
    const float* bo   = (const float*)d_in[6];
    float* out = (float*)d_out;

    float *p_y, *p_qkv, *p_att, *p_part, *wpr, *wqr, *wor;
    cudaGetSymbolAddress((void**)&p_y,   g_y);
    cudaGetSymbolAddress((void**)&p_qkv, g_qkv);
    cudaGetSymbolAddress((void**)&p_att, g_att);
    cudaGetSymbolAddress((void**)&p_part, g_part);
    cudaGetSymbolAddress((void**)&wpr, g_Wp_r);
    cudaGetSymbolAddress((void**)&wqr, g_Wq_r);
    cudaGetSymbolAddress((void**)&wor, g_Wo_r);

    const int natten_smem = (127 * RS * 2 + TQ * RS + 8 * PTROWS * PTS) * 4;
    static bool attr_set = false;
    if (!attr_set) {
        cudaFuncSetAttribute(natten_kernel,
                             cudaFuncAttributeMaxDynamicSharedMemorySize, natten_smem);
        cudaFuncSetAttribute(gemm_tf32_kernel<true, false, 4>,
                             cudaFuncAttributeMaxDynamicSharedMemorySize, GSMEM);
        cudaFuncSetAttribute(gemm_tf32_kernel<false, false, 1>,
                             cudaFuncAttributeMaxDynamicSharedMemorySize, GSMEM);
        cudaFuncSetAttribute(gemm_tf32_kernel<false, false, 2>,
                             cudaFuncAttributeMaxDynamicSharedMemorySize, GSMEM);
        attr_set = true;
    }

    prep_weights_kernel<<<(FIN * CDIM + 255) / 256, 256>>>(Wp, wpr, FIN * CDIM);
    prep_weights_kernel<<<(CDIM * C3 + 255) / 256, 256>>>(Wqkv, wqr, CDIM * C3);
    prep_weights_kernel<<<(CDIM * CDIM + 255) / 256, 256>>>(Wo, wor, CDIM * CDIM);

    // y = x @ Wp + bp : split-K=4 partials, reduce (+bias, tf32-round)
    gemm_tf32_kernel<true, false, 4>
        <<<dim3(CDIM / 128, LSEQ / 128, 4), 256, GSMEM>>>(
        x, wpr, nullptr, p_part, LSEQ, CDIM, FIN);
    reduce_kernel<4, true><<<(LSEQ * CDIM / 4 + 255) / 256, 256>>>(
        p_part, bp, p_y, LSEQ, CDIM);

    // qkv = y @ Wqkv + bqkv : single pass, grid 384
    gemm_tf32_kernel<false, false, 1>
        <<<dim3(C3 / 128, LSEQ / 128), 256, GSMEM>>>(
        p_y, wqr, bqkv, p_qkv, LSEQ, C3, CDIM);

    natten_kernel<<<dim3(LSEQ / TQ, NH), 256, natten_smem>>>(p_qkv, p_att);

    // out = att @ Wo + bo : split-K=2 partials, reduce (+bias)
    gemm_tf32_kernel<false, false, 2>
        <<<dim3(CDIM / 128, LSEQ / 128, 2), 256, GSMEM>>>(
        p_att, wor, nullptr, p_part, LSEQ, CDIM, CDIM);
    reduce_kernel<2, false><<<(LSEQ * CDIM / 4 + 255) / 256, 256>>>(
        p_part, bo, out, LSEQ, CDIM);
}

// round 12
// speedup vs baseline: 1.1308x; 1.1308x over previous
#include <cuda_runtime.h>
#include <cuda_bf16.h>
#include <cstdint>

#define LSEQ 8192
#define FIN  1024
#define CDIM 256
#define C3   768
#define NH   8
#define DH   32
#define KS   63

__device__ float g_y[LSEQ * CDIM];
__device__ float g_qkv[LSEQ * C3];
__device__ float g_att[LSEQ * CDIM];

// Fragment-permuted tf32-rounded weights: Bp[k8][n8][lane][slot]
// Bp[((k8)*(N/8)+(n8))*64 + lane*2 + slot] = round_tf32(W[(k8*8 + slot*4 + (lane&3))*N + n8*8 + (lane>>2)])
__device__ float g_Wp_p[(FIN / 8) * (CDIM / 8) * 64];
__device__ float g_Wq_p[(CDIM / 8) * (C3 / 8) * 64];
__device__ float g_Wo_p[(CDIM / 8) * (CDIM / 8) * 64];

// ---------------------------------------------------------------------------
// helpers
// ---------------------------------------------------------------------------
__device__ __forceinline__ void cp16(void* smem, const void* g) {
    uint32_t s = (uint32_t)__cvta_generic_to_shared(smem);
    asm volatile("cp.async.cg.shared.global [%0], [%1], 16;\n" :: "r"(s), "l"(g));
}
__device__ __forceinline__ void cp_commit() {
    asm volatile("cp.async.commit_group;\n");
}
__device__ __forceinline__ void mma_tf32(float* d, const uint32_t* a, const uint32_t* b) {
    asm volatile(
        "mma.sync.aligned.m16n8k8.row.col.f32.tf32.tf32.f32 "
        "{%0,%1,%2,%3}, {%4,%5,%6,%7}, {%8,%9}, {%0,%1,%2,%3};\n"
        : "+f"(d[0]), "+f"(d[1]), "+f"(d[2]), "+f"(d[3])
        : "r"(a[0]), "r"(a[1]), "r"(a[2]), "r"(a[3]), "r"(b[0]), "r"(b[1]));
}
__device__ __forceinline__ uint32_t cvt_rna_tf32(float x) {
    uint32_t r;
    asm("cvt.rna.tf32.f32 %0, %1;" : "=r"(r) : "f"(x));
    return r;
}
__device__ __forceinline__ float round_tf32(float x) {
    return __uint_as_float(cvt_rna_tf32(x));
}

// ---------------------------------------------------------------------------
// Weight prep: W[K][N] -> Bp fragment-permuted, tf32-RNE rounded.
// One thread per output element.
// ---------------------------------------------------------------------------
__global__ void prep_weights_kernel(const float* __restrict__ W,
                                    float* __restrict__ Bp, int K, int N)
{
    int idx = blockIdx.x * blockDim.x + threadIdx.x;
    int total = (K / 8) * (N / 8) * 64;
    if (idx >= total) return;
    int slot = idx & 1;
    int lane = (idx >> 1) & 31;
    int blk  = idx >> 6;              // k8 * (N/8) + n8
    int n8   = blk % (N / 8);
    int k8   = blk / (N / 8);
    int kk = k8 * 8 + slot * 4 + (lane & 3);
    int nn = n8 * 8 + (lane >> 2);
    Bp[idx] = round_tf32(W[(size_t)kk * N + nn]);
}

// ---------------------------------------------------------------------------
// TF32 GEMM: BM=128 BN=64 BK=16, 256 thr (8 warps, 4m x 2n), warp 32x32,
// 2-stage cp.async, B pre-permuted (LDS.64 frags), static smem (~28KB).
// ---------------------------------------------------------------------------
#define ASTRIDE 20

template<bool CVT_A, bool ROUND_OUT>
__global__ __launch_bounds__(256) void gemm_tf32_kernel(
    const float* __restrict__ A, const float* __restrict__ Bp,
    const float* __restrict__ bias, float* __restrict__ C,
    int M, int N, int K)
{
    __shared__ float As[2][128 * ASTRIDE];
    __shared__ float Bs[2][1024];          // 2 k8-steps x 8 n8 x 32 lanes x 2

    const int bm = blockIdx.y * 128;
    const int bn = blockIdx.x * 64;
    const int tid = threadIdx.x;
    const int wid = tid >> 5;
    const int lane = tid & 31;
    const int warp_m = wid & 3;            // 0..3
    const int warp_n = wid >> 2;           // 0..1
    const int r = lane >> 2;
    const int c = lane & 3;

    // A staging map (128 rows x 16 floats = 512 cp16; 2/thread)
    const int arow0 = tid >> 2;
    const int ac4   = (tid & 3) * 4;
    // B staging map (4KB = 256 cp16; 1/thread)
    const int bk8l  = tid >> 7;            // 0..1
    const int bn8l  = (tid >> 4) & 7;      // 0..7
    const int bpart = tid & 15;            // 16B chunk
    const int n8cnt = N >> 3;

    float acc[2][4][4];
    #pragma unroll
    for (int i = 0; i < 2; i++)
        #pragma unroll
        for (int j = 0; j < 4; j++)
            #pragma unroll
            for (int e = 0; e < 4; e++) acc[i][j][e] = 0.f;

    const int T = K >> 4;

    auto stage = [&](int kt, int s) {
        const int k0 = kt << 4;
        cp16(&As[s][arow0 * ASTRIDE + ac4], &A[(size_t)(bm + arow0) * K + k0 + ac4]);
        cp16(&As[s][(arow0 + 64) * ASTRIDE + ac4], &A[(size_t)(bm + arow0 + 64) * K + k0 + ac4]);
        cp16(&Bs[s][(bk8l * 8 + bn8l) * 64 + bpart * 4],
             &Bp[(size_t)(((k0 >> 3) + bk8l) * n8cnt + (bn >> 3) + bn8l) * 64 + bpart * 4]);
        cp_commit();
    };

    stage(0, 0);

    for (int kt = 0; kt < T; kt++) {
        const int buf = kt & 1;
        if (kt + 1 < T) {
            stage(kt + 1, buf ^ 1);
            asm volatile("cp.async.wait_group 1;\n");
        } else {
            asm volatile("cp.async.wait_group 0;\n");
        }
        __syncthreads();

        const float* as = As[buf];
        const float* bs = Bs[buf];
        #pragma unroll
        for (int ks = 0; ks < 16; ks += 8) {
            uint32_t af[2][4], bf[4][2];
            #pragma unroll
            for (int mi = 0; mi < 2; mi++) {
                int m0 = warp_m * 32 + mi * 16;
                float a0 = as[(m0 + r)     * ASTRIDE + ks + c];
                float a1 = as[(m0 + r + 8) * ASTRIDE + ks + c];
                float a2 = as[(m0 + r)     * ASTRIDE + ks + c + 4];
                float a3 = as[(m0 + r + 8) * ASTRIDE + ks + c + 4];
                if (CVT_A) {
                    af[mi][0] = cvt_rna_tf32(a0);
                    af[mi][1] = cvt_rna_tf32(a1);
                    af[mi][2] = cvt_rna_tf32(a2);
                    af[mi][3] = cvt_rna_tf32(a3);
                } else {
                    af[mi][0] = __float_as_uint(a0);
                    af[mi][1] = __float_as_uint(a1);
                    af[mi][2] = __float_as_uint(a2);
                    af[mi][3] = __float_as_uint(a3);
                }
            }
            const int k8l = ks >> 3;
            #pragma unroll
            for (int nj = 0; nj < 4; nj++) {
                // n8 local = warp_n*4 + nj ; LDS.64 of this thread's 2 frag values
                const float2 bb = *(const float2*)&bs[(k8l * 8 + warp_n * 4 + nj) * 64 + lane * 2];
                bf[nj][0] = __float_as_uint(bb.x);
                bf[nj][1] = __float_as_uint(bb.y);
            }
            #pragma unroll
            for (int mi = 0; mi < 2; mi++)
                #pragma unroll
                for (int nj = 0; nj < 4; nj++)
                    mma_tf32(acc[mi][nj], af[mi], bf[nj]);
        }
        __syncthreads();
    }

    #pragma unroll
    for (int mi = 0; mi < 2; mi++) {
        #pragma unroll
        for (int nj = 0; nj < 4; nj++) {
            int row = bm + warp_m * 32 + mi * 16 + r;
            int col = bn + warp_n * 32 + nj * 8 + c * 2;
            float2 bb = *(const float2*)&bias[col];
            float2 o0, o1;
            o0.x = acc[mi][nj][0] + bb.x;
            o0.y = acc[mi][nj][1] + bb.y;
            o1.x = acc[mi][nj][2] + bb.x;
            o1.y = acc[mi][nj][3] + bb.y;
            if (ROUND_OUT) {
                o0.x = round_tf32(o0.x); o0.y = round_tf32(o0.y);
                o1.x = round_tf32(o1.x); o1.y = round_tf32(o1.y);
            }
            *(float2*)&C[(size_t)row * N + col] = o0;
            *(float2*)&C[(size_t)(row + 8) * N + col] = o1;
        }
    }
}

// ---------------------------------------------------------------------------
// NATTEN-1D: float4 staging; phase A/B as round 4. att stored tf32-rounded.
// ---------------------------------------------------------------------------
#define TQ 64
#define KV 126
#define RS 36
#define PTS 12
#define PTROWS 72

__device__ __forceinline__ int win_start(int l) {
    int s = l - 31;
    if (s < 0) s = 0;
    if (s > LSEQ - KS) s = LSEQ - KS;
    return s;
}

__global__ __launch_bounds__(256) void natten_kernel(
    const float* __restrict__ qkv, float* __restrict__ out)
{
    extern __shared__ float sm[];
    float* Ks = sm;
    float* Vs = Ks + 127 * RS;
    float* Qs = Vs + 127 * RS;
    float* Pt = Qs + TQ * RS;

    const int t0 = blockIdx.x * TQ;
    const int h = blockIdx.y;
    const int tid = threadIdx.x;
    const int w = tid >> 5;
    const int lane = tid & 31;

    int base = t0 - 31;
    if (base < 0) base = 0;
    if (base > LSEQ - KV) base = LSEQ - KV;

    const float scale = 0.17677669529663687f;

    // K,V staging: float4 (126 rows x 8 chunks)
    for (int idx = tid; idx < KV * 8; idx += 256) {
        int row = idx >> 3;
        int d4 = (idx & 7) * 4;
        size_t g = (size_t)(base + row) * C3 + CDIM + h * DH + d4;
        *(float4*)&Ks[row * RS + d4] = *(const float4*)&qkv[g];
        *(float4*)&Vs[row * RS + d4] = *(const float4*)&qkv[g + CDIM];
    }
    if (tid < 32) {
        Ks[126 * RS + tid] = 0.f;
        Vs[126 * RS + tid] = 0.f;
    }
    // Q staging (pre-scaled), float4
    for (int idx = tid; idx < TQ * 8; idx += 256) {
        int row = idx >> 3;
        int d4 = (idx & 7) * 4;
        float4 q = *(const float4*)&qkv[(size_t)(t0 + row) * C3 + h * DH + d4];
        q.x *= scale; q.y *= scale; q.z *= scale; q.w *= scale;
        *(float4*)&Qs[row * RS + d4] = q;
    }
    for (int idx = tid; idx < 8 * PTROWS * PTS; idx += 256)
        Pt[idx] = 0.f;
    __syncthreads();

    const int l0 = t0 + w * 8;
    const int ws0 = win_start(l0) - base;
    const int ws7 = win_start(l0 + 7) - base;
    float* Ptw = Pt + w * PTROWS * PTS;

    #pragma unroll 1
    for (int qi = 0; qi < 8; qi++) {
        const int lq = w * 8 + qi;
        const int l = t0 + lq;
        const int ws = win_start(l) - base;

        const float4* k0p = (const float4*)&Ks[(ws + lane) * RS];
        const float4* k1p = (const float4*)&Ks[(ws + 32 + lane) * RS];
        const float4* qp  = (const float4*)&Qs[lq * RS];

        float s0 = 0.f, s1 = 0.f;
        #pragma unroll
        for (int d4 = 0; d4 < 8; d4++) {
            float4 q4 = qp[d4];
            float4 ka = k0p[d4];
            float4 kb = k1p[d4];
            s0 += q4.x * ka.x + q4.y * ka.y + q4.z * ka.z + q4.w * ka.w;
            s1 += q4.x * kb.x + q4.y * kb.y + q4.z * kb.z + q4.w * kb.w;
        }

        float m = fmaxf(s0, (lane < 31) ? s1 : -1e30f);
        #pragma unroll
        for (int o = 16; o > 0; o >>= 1)
            m = fmaxf(m, __shfl_xor_sync(0xffffffffu, m, o));
        float e0 = __expf(s0 - m);
        float e1 = (lane < 31) ? __expf(s1 - m) : 0.f;
        float sum = e0 + e1;
        #pragma unroll
        for (int o = 16; o > 0; o >>= 1)
            sum += __shfl_xor_sync(0xffffffffu, sum, o);
        float inv = __frcp_rn(sum);

        const int off = ws - ws0;
        Ptw[(off + lane) * PTS + qi]      = e0 * inv;
        Ptw[(off + 32 + lane) * PTS + qi] = e1 * inv;
    }
    __syncwarp();

    const int nU = ws7 - ws0 + 64;
    float acc[8];
    #pragma unroll
    for (int q = 0; q < 8; q++) acc[q] = 0.f;

    const float* vb = &Vs[ws0 * RS + lane];
    #pragma unroll 4
    for (int jj = 0; jj < nU; jj++) {
        float v = vb[jj * RS];
        float4 pa = *(const float4*)&Ptw[jj * PTS];
        float4 pb = *(const float4*)&Ptw[jj * PTS + 4];
        acc[0] = fmaf(pa.x, v, acc[0]);
        acc[1] = fmaf(pa.y, v, acc[1]);
        acc[2] = fmaf(pa.z, v, acc[2]);
        acc[3] = fmaf(pa.w, v, acc[3]);
        acc[4] = fmaf(pb.x, v, acc[4]);
        acc[5] = fmaf(pb.y, v, acc[5]);
        acc[6] = fmaf(pb.z, v, acc[6]);
        acc[7] = fmaf(pb.w, v, acc[7]);
    }

    #pragma unroll
    for (int q = 0; q < 8; q++)
        out[(size_t)(l0 + q) * CDIM + h * DH + lane] = round_tf32(acc[q]);
}

// ---------------------------------------------------------------------------
extern "C" void kernel_launch(void* const* d_in, const int* in_sizes, int n_in,
                              void* d_out, int out_size)
{
    const float* x    = (const float*)d_in[0];
    const float* Wp   = (const float*)d_in[1];
    const float* bp   = (const float*)d_in[2];
    const float* Wqkv = (const float*)d_in[3];
    const float* bqkv = (const float*)d_in[4];
    const float* Wo   = (const float*)d_in[5];
    const float* bo   = (const float*)d_in[6];
    float* out = (float*)d_out;

    float *p_y, *p_qkv, *p_att, *wpp, *wqp, *wop;
    cudaGetSymbolAddress((void**)&p_y,   g_y);
    cudaGetSymbolAddress((void**)&p_qkv, g_qkv);
    cudaGetSymbolAddress((void**)&p_att, g_att);
    cudaGetSymbolAddress((void**)&wpp, g_Wp_p);
    cudaGetSymbolAddress((void**)&wqp, g_Wq_p);
    cudaGetSymbolAddress((void**)&wop, g_Wo_p);

    const int natten_smem = (127 * RS * 2 + TQ * RS + 8 * PTROWS * PTS) * 4;
    static bool attr_set = false;
    if (!attr_set) {
        cudaFuncSetAttribute(natten_kernel,
                             cudaFuncAttributeMaxDynamicSharedMemorySize, natten_smem);
        attr_set = true;
    }

    // permute + round weights
    prep_weights_kernel<<<(FIN * CDIM + 255) / 256, 256>>>(Wp, wpp, FIN, CDIM);
    prep_weights_kernel<<<(CDIM * C3 + 255) / 256, 256>>>(Wqkv, wqp, CDIM, C3);
    prep_weights_kernel<<<(CDIM * CDIM + 255) / 256, 256>>>(Wo, wop, CDIM, CDIM);

    // y = x @ Wp + bp  (A=x cvt inline; y stored pre-rounded)
    gemm_tf32_kernel<true, true><<<dim3(CDIM / 64, LSEQ / 128), 256>>>(
        x, wpp, bp, p_y, LSEQ, CDIM, FIN);

    // qkv = y @ Wqkv + bqkv
    gemm_tf32_kernel<false, false><<<dim3(C3 / 64, LSEQ / 128), 256>>>(
        p_y, wqp, bqkv, p_qkv, LSEQ, C3, CDIM);

    natten_kernel<<<dim3(LSEQ / TQ, NH), 256, natten_smem>>>(p_qkv, p_att);

    // out = att @ Wo + bo
    gemm_tf32_kernel<false, false><<<dim3(CDIM / 64, LSEQ / 128), 256>>>(
        p_att, wop, bo, out, LSEQ, CDIM, CDIM);
}

// round 14
// speedup vs baseline: 1.2270x; 1.0851x over previous
#include <cuda_runtime.h>
#include <cuda_bf16.h>
#include <cstdint>

#define LSEQ 8192
#define FIN  1024
#define CDIM 256
#define C3   768
#define NH   8
#define DH   32
#define KS   63

__device__ float g_y[LSEQ * CDIM];
__device__ float g_qkv[LSEQ * C3];
__device__ float g_att[LSEQ * CDIM];

// Fragment-permuted tf32-rounded weights (round-12 layout)
__device__ float g_Wp_p[(FIN / 8) * (CDIM / 8) * 64];
__device__ float g_Wq_p[(CDIM / 8) * (C3 / 8) * 64];
__device__ float g_Wo_p[(CDIM / 8) * (CDIM / 8) * 64];

// ---------------------------------------------------------------------------
// helpers
// ---------------------------------------------------------------------------
__device__ __forceinline__ void cp16(void* smem, const void* g) {
    uint32_t s = (uint32_t)__cvta_generic_to_shared(smem);
    asm volatile("cp.async.cg.shared.global [%0], [%1], 16;\n" :: "r"(s), "l"(g));
}
__device__ __forceinline__ void cp_commit() {
    asm volatile("cp.async.commit_group;\n");
}
__device__ __forceinline__ void mma_tf32(float* d, const uint32_t* a, const uint32_t* b) {
    asm volatile(
        "mma.sync.aligned.m16n8k8.row.col.f32.tf32.tf32.f32 "
        "{%0,%1,%2,%3}, {%4,%5,%6,%7}, {%8,%9}, {%0,%1,%2,%3};\n"
        : "+f"(d[0]), "+f"(d[1]), "+f"(d[2]), "+f"(d[3])
        : "r"(a[0]), "r"(a[1]), "r"(a[2]), "r"(a[3]), "r"(b[0]), "r"(b[1]));
}
__device__ __forceinline__ uint32_t cvt_rna_tf32(float x) {
    uint32_t r;
    asm("cvt.rna.tf32.f32 %0, %1;" : "=r"(r) : "f"(x));
    return r;
}
__device__ __forceinline__ float round_tf32(float x) {
    return __uint_as_float(cvt_rna_tf32(x));
}

// ---------------------------------------------------------------------------
// Weight prep: W[K][N] -> Bp fragment-permuted, tf32-RNE rounded.
// ---------------------------------------------------------------------------
__global__ void prep_weights_kernel(const float* __restrict__ W,
                                    float* __restrict__ Bp, int K, int N)
{
    int idx = blockIdx.x * blockDim.x + threadIdx.x;
    int total = (K / 8) * (N / 8) * 64;
    if (idx >= total) return;
    int slot = idx & 1;
    int lane = (idx >> 1) & 31;
    int blk  = idx >> 6;
    int n8   = blk % (N / 8);
    int k8   = blk / (N / 8);
    int kk = k8 * 8 + slot * 4 + (lane & 3);
    int nn = n8 * 8 + (lane >> 2);
    Bp[idx] = round_tf32(W[(size_t)kk * N + nn]);
}

// ---------------------------------------------------------------------------
// TF32 GEMM (round-12, unchanged): BM=128 BN=64 BK=16, 2-stage, B permuted.
// ---------------------------------------------------------------------------
#define ASTRIDE 20

template<bool CVT_A, bool ROUND_OUT>
__global__ __launch_bounds__(256) void gemm_tf32_kernel(
    const float* __restrict__ A, const float* __restrict__ Bp,
    const float* __restrict__ bias, float* __restrict__ C,
    int M, int N, int K)
{
    __shared__ float As[2][128 * ASTRIDE];
    __shared__ float Bs[2][1024];

    const int bm = blockIdx.y * 128;
    const int bn = blockIdx.x * 64;
    const int tid = threadIdx.x;
    const int wid = tid >> 5;
    const int lane = tid & 31;
    const int warp_m = wid & 3;
    const int warp_n = wid >> 2;
    const int r = lane >> 2;
    const int c = lane & 3;

    const int arow0 = tid >> 2;
    const int ac4   = (tid & 3) * 4;
    const int bk8l  = tid >> 7;
    const int bn8l  = (tid >> 4) & 7;
    const int bpart = tid & 15;
    const int n8cnt = N >> 3;

    float acc[2][4][4];
    #pragma unroll
    for (int i = 0; i < 2; i++)
        #pragma unroll
        for (int j = 0; j < 4; j++)
            #pragma unroll
            for (int e = 0; e < 4; e++) acc[i][j][e] = 0.f;

    const int T = K >> 4;

    auto stage = [&](int kt, int s) {
        const int k0 = kt << 4;
        cp16(&As[s][arow0 * ASTRIDE + ac4], &A[(size_t)(bm + arow0) * K + k0 + ac4]);
        cp16(&As[s][(arow0 + 64) * ASTRIDE + ac4], &A[(size_t)(bm + arow0 + 64) * K + k0 + ac4]);
        cp16(&Bs[s][(bk8l * 8 + bn8l) * 64 + bpart * 4],
             &Bp[(size_t)(((k0 >> 3) + bk8l) * n8cnt + (bn >> 3) + bn8l) * 64 + bpart * 4]);
        cp_commit();
    };

    stage(0, 0);

    for (int kt = 0; kt < T; kt++) {
        const int buf = kt & 1;
        if (kt + 1 < T) {
            stage(kt + 1, buf ^ 1);
            asm volatile("cp.async.wait_group 1;\n");
        } else {
            asm volatile("cp.async.wait_group 0;\n");
        }
        __syncthreads();

        const float* as = As[buf];
        const float* bs = Bs[buf];
        #pragma unroll
        for (int ks = 0; ks < 16; ks += 8) {
            uint32_t af[2][4], bf[4][2];
            #pragma unroll
            for (int mi = 0; mi < 2; mi++) {
                int m0 = warp_m * 32 + mi * 16;
                float a0 = as[(m0 + r)     * ASTRIDE + ks + c];
                float a1 = as[(m0 + r + 8) * ASTRIDE + ks + c];
                float a2 = as[(m0 + r)     * ASTRIDE + ks + c + 4];
                float a3 = as[(m0 + r + 8) * ASTRIDE + ks + c + 4];
                if (CVT_A) {
                    af[mi][0] = cvt_rna_tf32(a0);
                    af[mi][1] = cvt_rna_tf32(a1);
                    af[mi][2] = cvt_rna_tf32(a2);
                    af[mi][3] = cvt_rna_tf32(a3);
                } else {
                    af[mi][0] = __float_as_uint(a0);
                    af[mi][1] = __float_as_uint(a1);
                    af[mi][2] = __float_as_uint(a2);
                    af[mi][3] = __float_as_uint(a3);
                }
            }
            const int k8l = ks >> 3;
            #pragma unroll
            for (int nj = 0; nj < 4; nj++) {
                const float2 bb = *(const float2*)&bs[(k8l * 8 + warp_n * 4 + nj) * 64 + lane * 2];
                bf[nj][0] = __float_as_uint(bb.x);
                bf[nj][1] = __float_as_uint(bb.y);
            }
            #pragma unroll
            for (int mi = 0; mi < 2; mi++)
                #pragma unroll
                for (int nj = 0; nj < 4; nj++)
                    mma_tf32(acc[mi][nj], af[mi], bf[nj]);
        }
        __syncthreads();
    }

    #pragma unroll
    for (int mi = 0; mi < 2; mi++) {
        #pragma unroll
        for (int nj = 0; nj < 4; nj++) {
            int row = bm + warp_m * 32 + mi * 16 + r;
            int col = bn + warp_n * 32 + nj * 8 + c * 2;
            float2 bb = *(const float2*)&bias[col];
            float2 o0, o1;
            o0.x = acc[mi][nj][0] + bb.x;
            o0.y = acc[mi][nj][1] + bb.y;
            o1.x = acc[mi][nj][2] + bb.x;
            o1.y = acc[mi][nj][3] + bb.y;
            if (ROUND_OUT) {
                o0.x = round_tf32(o0.x); o0.y = round_tf32(o0.y);
                o1.x = round_tf32(o1.x); o1.y = round_tf32(o1.y);
            }
            *(float2*)&C[(size_t)row * N + col] = o0;
            *(float2*)&C[(size_t)(row + 8) * N + col] = o1;
        }
    }
}

// ---------------------------------------------------------------------------
// NATTEN-1D v3: K stored dim-major (Kt[d][row], stride 137, conflict-free);
// phase A = d-tiled outer product, key loads amortized over all 8 queries.
// ---------------------------------------------------------------------------
#define TQ 64
#define KV 126
#define RS 36       // V/Q row stride
#define KTS 137     // Kt row stride (rows 0..136; 126+ zeroed)
#define PTS 12
#define PTROWS 72

__device__ __forceinline__ int win_start(int l) {
    int s = l - 31;
    if (s < 0) s = 0;
    if (s > LSEQ - KS) s = LSEQ - KS;
    return s;
}

__global__ __launch_bounds__(256) void natten_kernel(
    const float* __restrict__ qkv, float* __restrict__ out)
{
    extern __shared__ float sm[];
    float* Kt = sm;                       // 32 * 137
    float* Vs = Kt + 32 * KTS;            // 127 * 36
    float* Qs = Vs + 127 * RS;            // 64 * 36
    float* Pt = Qs + TQ * RS;             // 8 * 72 * 12

    const int t0 = blockIdx.x * TQ;
    const int h = blockIdx.y;
    const int tid = threadIdx.x;
    const int w = tid >> 5;
    const int lane = tid & 31;

    int base = t0 - 31;
    if (base < 0) base = 0;
    if (base > LSEQ - KV) base = LSEQ - KV;

    const float scale = 0.17677669529663687f;

    // K (transposed) + V staging, float4 gmem reads
    for (int idx = tid; idx < KV * 8; idx += 256) {
        int row = idx >> 3;
        int d4 = (idx & 7) * 4;
        size_t g = (size_t)(base + row) * C3 + CDIM + h * DH + d4;
        float4 kv = *(const float4*)&qkv[g];
        Kt[(d4 + 0) * KTS + row] = kv.x;
        Kt[(d4 + 1) * KTS + row] = kv.y;
        Kt[(d4 + 2) * KTS + row] = kv.z;
        Kt[(d4 + 3) * KTS + row] = kv.w;
        *(float4*)&Vs[row * RS + d4] = *(const float4*)&qkv[g + CDIM];
    }
    // zero Kt rows 126..136 and Vs row 126
    for (int idx = tid; idx < 32 * 11; idx += 256) {
        int d = idx & 31;
        int rr = 126 + (idx >> 5);
        Kt[d * KTS + rr] = 0.f;
    }
    if (tid < 32) Vs[126 * RS + tid] = 0.f;
    // Q staging (pre-scaled)
    for (int idx = tid; idx < TQ * 8; idx += 256) {
        int row = idx >> 3;
        int d4 = (idx & 7) * 4;
        float4 q = *(const float4*)&qkv[(size_t)(t0 + row) * C3 + h * DH + d4];
        q.x *= scale; q.y *= scale; q.z *= scale; q.w *= scale;
        *(float4*)&Qs[row * RS + d4] = q;
    }
    __syncthreads();

    const int l0 = t0 + w * 8;
    const int ws0 = win_start(l0) - base;
    const int off7 = win_start(l0 + 7) - base - ws0;    // 0..7
    float* Ptw = Pt + w * PTROWS * PTS;
    const bool lk7 = (lane < 7);

    // Phase A: d-tiled outer product. Lane = key (3 batches), regs = 8 queries.
    float s0[8], s1[8], s2[8];
    #pragma unroll
    for (int q = 0; q < 8; q++) { s0[q] = 0.f; s1[q] = 0.f; s2[q] = 0.f; }

    const float* qsw = &Qs[(w * 8) * RS];
    #pragma unroll 4
    for (int d = 0; d < 32; d++) {
        const float* ktd = &Kt[d * KTS + ws0 + lane];
        float k0 = ktd[0];
        float k1 = ktd[32];
        float k2 = lk7 ? ktd[64] : 0.f;
        #pragma unroll
        for (int q = 0; q < 8; q++) {
            float qd = qsw[q * RS + d];          // broadcast
            s0[q] = fmaf(qd, k0, s0[q]);
            s1[q] = fmaf(qd, k1, s1[q]);
            s2[q] = fmaf(qd, k2, s2[q]);
        }
    }

    // Softmax per query + transposed P store (unconditional: 0 when invalid)
    #pragma unroll 1
    for (int q = 0; q < 8; q++) {
        const int off = win_start(l0 + q) - base - ws0;   // 0..7
        const bool v0 = (lane >= off);
        const bool v1 = (lane <= off + 30);
        const bool v2 = (lane + 2 <= off);
        float a0 = v0 ? s0[q] : -1e30f;
        float a1 = v1 ? s1[q] : -1e30f;
        float a2 = v2 ? s2[q] : -1e30f;
        float m = fmaxf(fmaxf(a0, a1), a2);
        #pragma unroll
        for (int o = 16; o > 0; o >>= 1)
            m = fmaxf(m, __shfl_xor_sync(0xffffffffu, m, o));
        float e0 = v0 ? __expf(s0[q] - m) : 0.f;
        float e1 = v1 ? __expf(s1[q] - m) : 0.f;
        float e2 = v2 ? __expf(s2[q] - m) : 0.f;
        float sum = e0 + e1 + e2;
        #pragma unroll
        for (int o = 16; o > 0; o >>= 1)
            sum += __shfl_xor_sync(0xffffffffu, sum, o);
        float inv = __frcp_rn(sum);
        Ptw[lane * PTS + q]        = e0 * inv;
        Ptw[(lane + 32) * PTS + q] = e1 * inv;
        if (lk7) Ptw[(lane + 64) * PTS + q] = e2 * inv;
    }
    __syncwarp();

    // Phase B: union loop, lane = output dim
    const int nU = off7 + 64;
    float acc[8];
    #pragma unroll
    for (int q = 0; q < 8; q++) acc[q] = 0.f;

    const float* vb = &Vs[ws0 * RS + lane];
    #pragma unroll 4
    for (int jj = 0; jj < nU; jj++) {
        float v = vb[jj * RS];
        float4 pa = *(const float4*)&Ptw[jj * PTS];
        float4 pb = *(const float4*)&Ptw[jj * PTS + 4];
        acc[0] = fmaf(pa.x, v, acc[0]);
        acc[1] = fmaf(pa.y, v, acc[1]);
        acc[2] = fmaf(pa.z, v, acc[2]);
        acc[3] = fmaf(pa.w, v, acc[3]);
        acc[4] = fmaf(pb.x, v, acc[4]);
        acc[5] = fmaf(pb.y, v, acc[5]);
        acc[6] = fmaf(pb.z, v, acc[6]);
        acc[7] = fmaf(pb.w, v, acc[7]);
    }

    #pragma unroll
    for (int q = 0; q < 8; q++)
        out[(size_t)(l0 + q) * CDIM + h * DH + lane] = round_tf32(acc[q]);
}

// ---------------------------------------------------------------------------
extern "C" void kernel_launch(void* const* d_in, const int* in_sizes, int n_in,
                              void* d_out, int out_size)
{
    const float* x    = (const float*)d_in[0];
    const float* Wp   = (const float*)d_in[1];
    const float* bp   = (const float*)d_in[2];
    const float* Wqkv = (const float*)d_in[3];
    const float* bqkv = (const float*)d_in[4];
    const float* Wo   = (const float*)d_in[5];
    const float* bo   = (const float*)d_in[6];
    float* out = (float*)d_out;

    float *p_y, *p_qkv, *p_att, *wpp, *wqp, *wop;
    cudaGetSymbolAddress((void**)&p_y,   g_y);
    cudaGetSymbolAddress((void**)&p_qkv, g_qkv);
    cudaGetSymbolAddress((void**)&p_att, g_att);
    cudaGetSymbolAddress((void**)&wpp, g_Wp_p);
    cudaGetSymbolAddress((void**)&wqp, g_Wq_p);
    cudaGetSymbolAddress((void**)&wop, g_Wo_p);

    const int natten_smem = (32 * KTS + 127 * RS + TQ * RS + 8 * PTROWS * PTS) * 4;
    static bool attr_set = false;
    if (!attr_set) {
        cudaFuncSetAttribute(natten_kernel,
                             cudaFuncAttributeMaxDynamicSharedMemorySize, natten_smem);
        attr_set = true;
    }

    prep_weights_kernel<<<(FIN * CDIM + 255) / 256, 256>>>(Wp, wpp, FIN, CDIM);
    prep_weights_kernel<<<(CDIM * C3 + 255) / 256, 256>>>(Wqkv, wqp, CDIM, C3);
    prep_weights_kernel<<<(CDIM * CDIM + 255) / 256, 256>>>(Wo, wop, CDIM, CDIM);

    gemm_tf32_kernel<true, true><<<dim3(CDIM / 64, LSEQ / 128), 256>>>(
        x, wpp, bp, p_y, LSEQ, CDIM, FIN);

    gemm_tf32_kernel<false, false><<<dim3(C3 / 64, LSEQ / 128), 256>>>(
        p_y, wqp, bqkv, p_qkv, LSEQ, C3, CDIM);

    natten_kernel<<<dim3(LSEQ / TQ, NH), 256, natten_smem>>>(p_qkv, p_att);

    gemm_tf32_kernel<false, false><<<dim3(CDIM / 64, LSEQ / 128), 256>>>(
        p_att, wop, bo, out, LSEQ, CDIM, CDIM);
}